// round 1
// baseline (speedup 1.0000x reference)
#include <cuda_runtime.h>
#include <cuda_bf16.h>

// ---------------------------------------------------------------------------
// GraphLogitLayers: conv3x3(circular) + relu + global-mean-pool -> edge MLP ->
// node MLP -> logits.
// Shapes: P=4, B=128, C=32, H=W=64, HID=64. Images N = P*B = 512.
// Stage 1 (dominant): implicit-GEMM conv via bf16 mma.sync, fused
//                     bias+relu+pool, deterministic partial reduction.
// Stage 2: tiny graph MLP kernel.
// ---------------------------------------------------------------------------

#define NIMG   512
#define CIN    32
#define HH     64
#define WW     64
#define COUT   64
#define HID    64

// scratch (device globals; no allocation allowed)
__device__ alignas(16) float        g_partial[32 * NIMG * COUT];  // [slot][n][oc]
__device__ alignas(16) float        g_nodes[NIMG * COUT];         // pooled nodes
__device__ alignas(16) __nv_bfloat16 g_wb[9 * COUT * CIN];        // [tap][oc][ic] bf16

// ---------------------------------------------------------------------------
// prep: convert conv weights fp32 -> bf16, layout [tap][oc][ic]
// ---------------------------------------------------------------------------
__global__ void prep_kernel(const float* __restrict__ conv_w) {
    int i = blockIdx.x * blockDim.x + threadIdx.x;
    if (i < 9 * COUT * CIN) {
        int ic  = i & 31;
        int oc  = (i >> 5) & 63;
        int tap = i >> 11;           // 2048 per tap
        int kh = tap / 3, kw = tap % 3;
        g_wb[i] = __float2bfloat16(conv_w[((oc * CIN + ic) * 3 + kh) * 3 + kw]);
    }
}

// ---------------------------------------------------------------------------
// mma.sync m16n8k16 bf16 -> f32
// ---------------------------------------------------------------------------
__device__ __forceinline__ void mma_bf16(float* c, const unsigned* a,
                                         unsigned b0, unsigned b1) {
    asm volatile(
        "mma.sync.aligned.m16n8k16.row.col.f32.bf16.bf16.f32 "
        "{%0,%1,%2,%3}, {%4,%5,%6,%7}, {%8,%9}, {%0,%1,%2,%3};\n"
        : "+f"(c[0]), "+f"(c[1]), "+f"(c[2]), "+f"(c[3])
        : "r"(a[0]), "r"(a[1]), "r"(a[2]), "r"(a[3]), "r"(b0), "r"(b1));
}

__device__ __forceinline__ unsigned ld32h(const __nv_bfloat16* p) {
    return *reinterpret_cast<const unsigned*>(p);
}

// ---------------------------------------------------------------------------
// Fused conv + bias + relu + spatial-sum (partial).
// Grid: (16 row-tiles, 512 images). Block: 256 threads (8 warps).
// Block tile: 4 output rows x 64 cols x 64 oc.
// Warp tile: 16 oc x 128 spatial. Per tap: Out[oc,sp] += W[oc,ic] @ In[ic,sp].
// Smem input tile: 6 rows x 66 cols (halo, circular) x ic, ic padded 32->40
// (80B spatial stride = 20 banks -> conflict-free fragment loads).
// ---------------------------------------------------------------------------
#define ICP 40                      // padded ic stride (elements)

__global__ __launch_bounds__(256, 2)
void conv_pool_kernel(const float* __restrict__ x, const float* __restrict__ conv_b) {
    __shared__ alignas(16) __nv_bfloat16 tile[6 * 66 * ICP];   // 31680 B

    const int n  = blockIdx.y;
    const int rt = blockIdx.x;
    const int h0 = rt * 4;
    const int tid = threadIdx.x;

    const float* xb = x + ((long)n << 17);   // n * 32 * 4096

    // ---- load input tile (bf16 convert), circular rows; interior cols ----
    for (int idx = tid; idx < 6 * CIN * WW; idx += 256) {
        int w    = idx & 63;
        int rest = idx >> 6;
        int ic   = rest & 31;
        int rr   = rest >> 5;                       // 0..5
        int gh   = (h0 + rr + 63) & 63;             // h0 - 1 + rr (mod 64)
        tile[(rr * 66 + w + 1) * ICP + ic] =
            __float2bfloat16(xb[(ic << 12) + (gh << 6) + w]);
    }
    // halo columns (circular in w)
    for (int idx = tid; idx < 6 * CIN * 2; idx += 256) {
        int side = idx & 1;
        int rest = idx >> 1;
        int ic   = rest & 31;
        int rr   = rest >> 5;
        int gh   = (h0 + rr + 63) & 63;
        int gw   = side ? 0 : 63;
        int c    = side ? 65 : 0;
        tile[(rr * 66 + c) * ICP + ic] =
            __float2bfloat16(xb[(ic << 12) + (gh << 6) + gw]);
    }
    __syncthreads();

    const int lane   = tid & 31;
    const int warp   = tid >> 5;
    const int warpOc = warp & 3;         // 4 oc groups of 16
    const int warpSp = warp >> 2;        // 2 spatial halves of 128
    const int ocBase = warpOc << 4;
    const int grp    = lane >> 2;        // groupID (row / col-n)
    const int kcol   = (lane & 3) << 1;  // 2*threadID_in_group

    float acc[16][4];
#pragma unroll
    for (int t = 0; t < 16; t++)
#pragma unroll
        for (int j = 0; j < 4; j++) acc[t][j] = 0.f;

    // per-ntile smem base (half-element index), before tap/kstep offsets
    int tb[16];
#pragma unroll
    for (int t = 0; t < 16; t++) {
        int sp = warpSp * 128 + t * 8 + grp;           // tile lies in one row
        tb[t] = ((sp >> 6) * 66 + (sp & 63)) * ICP + kcol;
    }
    const int m0 = ocBase + grp;

    for (int kh = 0; kh < 3; kh++) {
        for (int kw = 0; kw < 3; kw++) {
            const __nv_bfloat16* wp = g_wb + (kh * 3 + kw) * (COUT * CIN);
            unsigned a[2][4];
#pragma unroll
            for (int ks = 0; ks < 2; ks++) {
                int base = m0 * CIN + ks * 16 + kcol;
                a[ks][0] = ld32h(wp + base);             // (m,   k)
                a[ks][1] = ld32h(wp + base + 8 * CIN);   // (m+8, k)
                a[ks][2] = ld32h(wp + base + 8);         // (m,   k+8)
                a[ks][3] = ld32h(wp + base + 8 * CIN + 8);
            }
            const int toff = (kh * 66 + kw) * ICP;
#pragma unroll
            for (int t = 0; t < 16; t++) {
#pragma unroll
                for (int ks = 0; ks < 2; ks++) {
                    const __nv_bfloat16* p = tile + tb[t] + toff + ks * 16;
                    unsigned b0 = ld32h(p);
                    unsigned b1 = ld32h(p + 8);
                    mma_bf16(acc[t], a[ks], b0, b1);
                }
            }
        }
    }

    // ---- epilogue: bias + relu per element, sum over spatial ----
    const float bias0 = conv_b[m0];
    const float bias1 = conv_b[m0 + 8];
    float s0 = 0.f, s1 = 0.f;
#pragma unroll
    for (int t = 0; t < 16; t++) {
        s0 += fmaxf(acc[t][0] + bias0, 0.f) + fmaxf(acc[t][1] + bias0, 0.f);
        s1 += fmaxf(acc[t][2] + bias1, 0.f) + fmaxf(acc[t][3] + bias1, 0.f);
    }
    // reduce over the 4 lanes sharing the same rows (lane%4 = n columns)
    s0 += __shfl_xor_sync(0xffffffffu, s0, 1);
    s0 += __shfl_xor_sync(0xffffffffu, s0, 2);
    s1 += __shfl_xor_sync(0xffffffffu, s1, 1);
    s1 += __shfl_xor_sync(0xffffffffu, s1, 2);

    if ((lane & 3) == 0) {
        int slot = rt * 2 + warpSp;                    // 0..31, unique writer
        g_partial[slot * (NIMG * COUT) + (n << 6) + m0]     = s0;
        g_partial[slot * (NIMG * COUT) + (n << 6) + m0 + 8] = s1;
    }
}

// ---------------------------------------------------------------------------
// deterministic reduction of 32 partial slots -> pooled nodes (mean /4096)
// ---------------------------------------------------------------------------
__global__ void reduce_nodes_kernel() {
    int i = blockIdx.x * blockDim.x + threadIdx.x;   // 32768 total
    float s = 0.f;
#pragma unroll
    for (int k = 0; k < 32; k++) s += g_partial[k * (NIMG * COUT) + i];
    g_nodes[i] = s * (1.f / 4096.f);
}

// ---------------------------------------------------------------------------
// Graph MLP. One block per (b, j-recv-node), 64 threads (one per hid unit).
// nodes[b][p][h] = g_nodes[(p*128 + b)*64 + h]
// ---------------------------------------------------------------------------
__global__ void mlp_kernel(const float* __restrict__ e_w1, const float* __restrict__ e_b1,
                           const float* __restrict__ e_w2, const float* __restrict__ e_b2,
                           const float* __restrict__ o_w1, const float* __restrict__ o_b1,
                           const float* __restrict__ o_w2, const float* __restrict__ o_b2,
                           float* __restrict__ out) {
    const int b = blockIdx.x >> 2;
    const int j = blockIdx.x & 3;
    const int h = threadIdx.x;      // 0..63

    __shared__ float sA[HID];   // send node (per i)
    __shared__ float sB[HID];   // recv node (j)
    __shared__ float sE[HID];   // e1 buffer
    __shared__ float sM[HID];   // msg / o buffer

    sB[h] = g_nodes[(j * 128 + b) * HID + h];

    float msg = 0.f;
    for (int i = 0; i < 4; i++) {
        sA[h] = g_nodes[(i * 128 + b) * HID + h];
        __syncthreads();
        float a1 = e_b1[h];
#pragma unroll 4
        for (int k = 0; k < HID; k++) a1 = fmaf(sA[k], e_w1[k * HID + h], a1);
#pragma unroll 4
        for (int k = 0; k < HID; k++) a1 = fmaf(sB[k], e_w1[(HID + k) * HID + h], a1);
        sE[h] = fmaxf(a1, 0.f);
        __syncthreads();
        float a2 = e_b2[h];
#pragma unroll 4
        for (int k = 0; k < HID; k++) a2 = fmaf(sE[k], e_w2[k * HID + h], a2);
        msg += fmaxf(a2, 0.f);
        __syncthreads();   // before sA/sE overwritten next iter
    }
    sM[h] = msg * 0.25f;
    __syncthreads();
    float a3 = o_b1[h];
#pragma unroll 4
    for (int k = 0; k < HID; k++) a3 = fmaf(sM[k], o_w1[k * HID + h], a3);
    float o = fmaxf(a3, 0.f);
    sA[h] = o * o_w2[h];
    __syncthreads();
    if (h == 0) {
        float s = o_b2[0];
#pragma unroll
        for (int k = 0; k < HID; k++) s += sA[k];
        out[b * 4 + j] = s;
    }
}

// ---------------------------------------------------------------------------
extern "C" void kernel_launch(void* const* d_in, const int* in_sizes, int n_in,
                              void* d_out, int out_size) {
    const float* x      = (const float*)d_in[0];
    const float* conv_w = (const float*)d_in[1];
    const float* conv_b = (const float*)d_in[2];
    const float* e_w1   = (const float*)d_in[3];
    const float* e_b1   = (const float*)d_in[4];
    const float* e_w2   = (const float*)d_in[5];
    const float* e_b2   = (const float*)d_in[6];
    const float* o_w1   = (const float*)d_in[7];
    const float* o_b1   = (const float*)d_in[8];
    const float* o_w2   = (const float*)d_in[9];
    const float* o_b2   = (const float*)d_in[10];
    float* out = (float*)d_out;

    prep_kernel<<<(9 * COUT * CIN + 255) / 256, 256>>>(conv_w);

    dim3 grid(16, NIMG);
    conv_pool_kernel<<<grid, 256>>>(x, conv_b);

    reduce_nodes_kernel<<<(NIMG * COUT) / 256, 256>>>();

    mlp_kernel<<<128 * 4, HID>>>(e_w1, e_b1, e_w2, e_b2,
                                 o_w1, o_b1, o_w2, o_b2, out);
}

// round 3
// speedup vs baseline: 1.1481x; 1.1481x over previous
#include <cuda_runtime.h>
#include <cuda_bf16.h>

// ---------------------------------------------------------------------------
// GraphLogitLayers: conv3x3(circular)+relu+mean-pool -> edge MLP -> node MLP.
// P=4, B=128, C=32, H=W=64, HID=64. NIMG = 512.
// Conv: implicit-GEMM bf16 mma.sync, ldmatrix B loads, fragment-packed A,
//       warp tile 32oc x 64sp, fused bias+relu+pool partials.
// ---------------------------------------------------------------------------

#define NIMG   512
#define CIN    32
#define WW     64
#define COUT   64
#define HID    64
#define NSLOT  64          // 16 row-tiles * 4 sp-warps

// device scratch (no allocations allowed)
__device__ alignas(16) float g_partial[NSLOT * NIMG * COUT];   // 8 MB
__device__ alignas(16) float g_nodes[NIMG * COUT];
__device__ alignas(16) uint4 g_wa[9 * 2 * 4 * 32];             // [tap][ks][mt][lane]

// ---------------------------------------------------------------------------
// prep: pack conv weights into mma A-fragment order (bf16x2 per reg, uint4 per
// lane): reg r of lane l for (tap, ks, mt):
//   m = mt*16 + (r&1)*8 + (l>>2),  k = ks*16 + (r>>1)*8 + 2*(l&3) (+1 hi half)
// ---------------------------------------------------------------------------
__global__ void prep_kernel(const float* __restrict__ w) {
    int i = blockIdx.x * blockDim.x + threadIdx.x;
    if (i >= 2304) return;
    int lane = i & 31;
    int mt   = (i >> 5) & 3;
    int ks   = (i >> 7) & 1;
    int tap  = i >> 8;
    int kh = tap / 3, kw = tap % 3;
    unsigned r[4];
#pragma unroll
    for (int rr = 0; rr < 4; rr++) {
        int m = mt * 16 + ((rr & 1) << 3) + (lane >> 2);
        int k = ks * 16 + ((rr >> 1) << 3) + ((lane & 3) << 1);
        unsigned lo = __bfloat16_as_ushort(__float2bfloat16(w[((m * CIN + k    ) * 3 + kh) * 3 + kw]));
        unsigned hi = __bfloat16_as_ushort(__float2bfloat16(w[((m * CIN + k + 1) * 3 + kh) * 3 + kw]));
        r[rr] = lo | (hi << 16);
    }
    g_wa[i] = make_uint4(r[0], r[1], r[2], r[3]);
}

// ---------------------------------------------------------------------------
__device__ __forceinline__ void mma_bf16(float* c, const unsigned* a,
                                         unsigned b0, unsigned b1) {
    asm volatile(
        "mma.sync.aligned.m16n8k16.row.col.f32.bf16.bf16.f32 "
        "{%0,%1,%2,%3}, {%4,%5,%6,%7}, {%8,%9}, {%0,%1,%2,%3};\n"
        : "+f"(c[0]), "+f"(c[1]), "+f"(c[2]), "+f"(c[3])
        : "r"(a[0]), "r"(a[1]), "r"(a[2]), "r"(a[3]), "r"(b0), "r"(b1));
}

__device__ __forceinline__ void ldsm_x4(unsigned& r0, unsigned& r1,
                                        unsigned& r2, unsigned& r3, unsigned addr) {
    asm volatile("ldmatrix.sync.aligned.m8n8.x4.shared.b16 {%0,%1,%2,%3}, [%4];\n"
                 : "=r"(r0), "=r"(r1), "=r"(r2), "=r"(r3) : "r"(addr));
}

// ---------------------------------------------------------------------------
// Fused conv + bias + relu + spatial partial-sum.
// Grid (16 row-tiles, 512 imgs), 256 threads (8 warps).
// Block tile: 4 rows x 64 cols x 64 oc. Warp: 32 oc x 64 sp (one row).
// Smem: 6 rows x 66 cols (circular halo) x ic, ic padded to ICP=40
// (80B spatial stride -> conflict-free ldmatrix row fetches).
// ---------------------------------------------------------------------------
#define ICP 40

__global__ __launch_bounds__(256, 2)
void conv_pool_kernel(const float* __restrict__ x, const float* __restrict__ conv_b) {
    __shared__ alignas(16) __nv_bfloat16 tile[6 * 66 * ICP];   // 31680 B

    const int n   = blockIdx.y;
    const int rt  = blockIdx.x;
    const int h0  = rt * 4;
    const int tid = threadIdx.x;
    const float* xb = x + ((long)n << 17);

    // interior columns
    for (int idx = tid; idx < 6 * CIN * WW; idx += 256) {
        int w    = idx & 63;
        int rest = idx >> 6;
        int ic   = rest & 31;
        int rr   = rest >> 5;
        int gh   = (h0 + rr + 63) & 63;
        tile[(rr * 66 + w + 1) * ICP + ic] =
            __float2bfloat16(xb[(ic << 12) + (gh << 6) + w]);
    }
    // circular halo columns
    for (int idx = tid; idx < 6 * CIN * 2; idx += 256) {
        int side = idx & 1;
        int rest = idx >> 1;
        int ic   = rest & 31;
        int rr   = rest >> 5;
        int gh   = (h0 + rr + 63) & 63;
        int gw   = side ? 0 : 63;
        int c    = side ? 65 : 0;
        tile[(rr * 66 + c) * ICP + ic] =
            __float2bfloat16(xb[(ic << 12) + (gh << 6) + gw]);
    }
    __syncthreads();

    const int lane   = tid & 31;
    const int warp   = tid >> 5;
    const int warpOc = warp & 1;     // 2 oc groups of 32
    const int warpSp = warp >> 1;    // 4 sp groups = block-tile rows

    // ldmatrix lane address: col = nt*8 + (lane&7), ic = (lane>>3)*8
    unsigned sbase = (unsigned)__cvta_generic_to_shared(tile) +
                     (((warpSp * 66 + (lane & 7)) * ICP + ((lane >> 3) << 3)) << 1);

    float acc[8][2][4];
#pragma unroll
    for (int nt = 0; nt < 8; nt++)
#pragma unroll
        for (int mt = 0; mt < 2; mt++)
#pragma unroll
            for (int c = 0; c < 4; c++) acc[nt][mt][c] = 0.f;

    for (int kh = 0; kh < 3; kh++) {
        for (int kw = 0; kw < 3; kw++) {
            const int tap = kh * 3 + kw;
            // A fragments: [tap][ks][mtGlobal][lane]
            uint4 a00 = g_wa[((tap * 2 + 0) * 4 + warpOc * 2 + 0) * 32 + lane]; // ks0 mt0
            uint4 a01 = g_wa[((tap * 2 + 0) * 4 + warpOc * 2 + 1) * 32 + lane]; // ks0 mt1
            uint4 a10 = g_wa[((tap * 2 + 1) * 4 + warpOc * 2 + 0) * 32 + lane]; // ks1 mt0
            uint4 a11 = g_wa[((tap * 2 + 1) * 4 + warpOc * 2 + 1) * 32 + lane]; // ks1 mt1
            unsigned tapaddr = sbase + (unsigned)(((kh * 66 + kw) * ICP) << 1);
#pragma unroll
            for (int nt = 0; nt < 8; nt++) {
                unsigned b0, b1, b2, b3;
                ldsm_x4(b0, b1, b2, b3, tapaddr + nt * (8 * ICP * 2));
                mma_bf16(acc[nt][0], (const unsigned*)&a00, b0, b1);
                mma_bf16(acc[nt][1], (const unsigned*)&a01, b0, b1);
                mma_bf16(acc[nt][0], (const unsigned*)&a10, b2, b3);
                mma_bf16(acc[nt][1], (const unsigned*)&a11, b2, b3);
            }
        }
    }

    // epilogue: bias + relu + sum over spatial, reduce over (lane&3)
    const int rowa = lane >> 2;
#pragma unroll
    for (int mt = 0; mt < 2; mt++) {
        int oc = warpOc * 32 + mt * 16 + rowa;
        float bs0 = conv_b[oc];
        float bs1 = conv_b[oc + 8];
        float s0 = 0.f, s1 = 0.f;
#pragma unroll
        for (int nt = 0; nt < 8; nt++) {
            s0 += fmaxf(acc[nt][mt][0] + bs0, 0.f) + fmaxf(acc[nt][mt][1] + bs0, 0.f);
            s1 += fmaxf(acc[nt][mt][2] + bs1, 0.f) + fmaxf(acc[nt][mt][3] + bs1, 0.f);
        }
        s0 += __shfl_xor_sync(0xffffffffu, s0, 1);
        s0 += __shfl_xor_sync(0xffffffffu, s0, 2);
        s1 += __shfl_xor_sync(0xffffffffu, s1, 1);
        s1 += __shfl_xor_sync(0xffffffffu, s1, 2);
        if ((lane & 3) == 0) {
            int slot = rt * 4 + warpSp;
            g_partial[slot * (NIMG * COUT) + (n << 6) + oc]     = s0;
            g_partial[slot * (NIMG * COUT) + (n << 6) + oc + 8] = s1;
        }
    }
}

// ---------------------------------------------------------------------------
__global__ void reduce_nodes_kernel() {
    int i = blockIdx.x * blockDim.x + threadIdx.x;   // 32768
    float s = 0.f;
#pragma unroll
    for (int k = 0; k < NSLOT; k++) s += g_partial[k * (NIMG * COUT) + i];
    g_nodes[i] = s * (1.f / 4096.f);
}

// ---------------------------------------------------------------------------
// Graph MLP: one block per batch b; 256 threads = 4 recv-nodes j x 64 hid h.
// nodes[b][p][h] = g_nodes[(p*128+b)*64+h]
// ---------------------------------------------------------------------------
__global__ __launch_bounds__(256)
void mlp_kernel(const float* __restrict__ e_w1, const float* __restrict__ e_b1,
                const float* __restrict__ e_w2, const float* __restrict__ e_b2,
                const float* __restrict__ o_w1, const float* __restrict__ o_b1,
                const float* __restrict__ o_w2, const float* __restrict__ o_b2,
                float* __restrict__ out) {
    const int b = blockIdx.x;
    const int j = threadIdx.x >> 6;
    const int h = threadIdx.x & 63;

    __shared__ float sN[4][HID];
    __shared__ float sE[4][HID];
    __shared__ float sM[4][HID];

    sN[j][h] = g_nodes[(j * 128 + b) * HID + h];
    __syncthreads();

    float msg = 0.f;
    for (int i = 0; i < 4; i++) {
        float p0 = e_b1[h], p1 = 0.f;
#pragma unroll 8
        for (int k = 0; k < HID; k += 2) {
            p0 = fmaf(sN[i][k],     e_w1[k * HID + h],       p0);
            p1 = fmaf(sN[i][k + 1], e_w1[(k + 1) * HID + h], p1);
        }
#pragma unroll 8
        for (int k = 0; k < HID; k += 2) {
            p0 = fmaf(sN[j][k],     e_w1[(HID + k) * HID + h],     p0);
            p1 = fmaf(sN[j][k + 1], e_w1[(HID + k + 1) * HID + h], p1);
        }
        sE[j][h] = fmaxf(p0 + p1, 0.f);
        __syncthreads();
        float q0 = e_b2[h], q1 = 0.f;
#pragma unroll 8
        for (int k = 0; k < HID; k += 2) {
            q0 = fmaf(sE[j][k],     e_w2[k * HID + h],       q0);
            q1 = fmaf(sE[j][k + 1], e_w2[(k + 1) * HID + h], q1);
        }
        msg += fmaxf(q0 + q1, 0.f);
        __syncthreads();
    }
    sM[j][h] = msg * 0.25f;
    __syncthreads();

    float q0 = o_b1[h], q1 = 0.f;
#pragma unroll 8
    for (int k = 0; k < HID; k += 2) {
        q0 = fmaf(sM[j][k],     o_w1[k * HID + h],       q0);
        q1 = fmaf(sM[j][k + 1], o_w1[(k + 1) * HID + h], q1);
    }
    float o = fmaxf(q0 + q1, 0.f);
    sE[j][h] = o * o_w2[h];
    __syncthreads();
    if (h == 0) {
        float s = o_b2[0];
#pragma unroll
        for (int k = 0; k < HID; k++) s += sE[j][k];
        out[b * 4 + j] = s;
    }
}

// ---------------------------------------------------------------------------
extern "C" void kernel_launch(void* const* d_in, const int* in_sizes, int n_in,
                              void* d_out, int out_size) {
    const float* x      = (const float*)d_in[0];
    const float* conv_w = (const float*)d_in[1];
    const float* conv_b = (const float*)d_in[2];
    const float* e_w1   = (const float*)d_in[3];
    const float* e_b1   = (const float*)d_in[4];
    const float* e_w2   = (const float*)d_in[5];
    const float* e_b2   = (const float*)d_in[6];
    const float* o_w1   = (const float*)d_in[7];
    const float* o_b1   = (const float*)d_in[8];
    const float* o_w2   = (const float*)d_in[9];
    const float* o_b2   = (const float*)d_in[10];
    float* out = (float*)d_out;

    prep_kernel<<<9, 256>>>(conv_w);

    dim3 grid(16, NIMG);
    conv_pool_kernel<<<grid, 256>>>(x, conv_b);

    reduce_nodes_kernel<<<(NIMG * COUT) / 256, 256>>>();

    mlp_kernel<<<128, 256>>>(e_w1, e_b1, e_w2, e_b2,
                             o_w1, o_b1, o_w2, o_b2, out);
}

// round 6
// speedup vs baseline: 1.1890x; 1.0357x over previous
#include <cuda_runtime.h>
#include <cuda_bf16.h>

// ---------------------------------------------------------------------------
// GraphLogitLayers: conv3x3(circular)+relu+mean-pool -> edge MLP -> node MLP.
// P=4, B=128, C=32, H=W=64, HID=64. NIMG = 512.
// NOTE: harness PTX virtual target is compute_103 (no 'a' feature) => tcgen05
// unavailable; mma.sync implicit-GEMM conv is the ceiling (~284us HMMA floor).
// Conv: implicit-GEMM bf16 mma.sync, ldmatrix B loads, fragment-packed A,
//       warp tile 32oc x 64sp, fused bias+relu+pool partials. (proven R3)
// MLP:  smem-staged weights + rank-1 edge decomposition (new).
// ---------------------------------------------------------------------------

#define NIMG   512
#define CIN    32
#define WW     64
#define COUT   64
#define HID    64
#define NSLOT  64          // 16 row-tiles * 4 sp-warps

// device scratch (no allocations allowed)
__device__ alignas(16) float g_partial[NSLOT * NIMG * COUT];   // 8 MB
__device__ alignas(16) float g_nodes[NIMG * COUT];
__device__ alignas(16) uint4 g_wa[9 * 2 * 4 * 32];             // [tap][ks][mt][lane]

// ---------------------------------------------------------------------------
// prep: pack conv weights into mma A-fragment order (bf16x2 per reg, uint4 per
// lane): reg r of lane l for (tap, ks, mt):
//   m = mt*16 + (r&1)*8 + (l>>2),  k = ks*16 + (r>>1)*8 + 2*(l&3) (+1 hi half)
// ---------------------------------------------------------------------------
__global__ void prep_kernel(const float* __restrict__ w) {
    int i = blockIdx.x * blockDim.x + threadIdx.x;
    if (i >= 2304) return;
    int lane = i & 31;
    int mt   = (i >> 5) & 3;
    int ks   = (i >> 7) & 1;
    int tap  = i >> 8;
    int kh = tap / 3, kw = tap % 3;
    unsigned r[4];
#pragma unroll
    for (int rr = 0; rr < 4; rr++) {
        int m = mt * 16 + ((rr & 1) << 3) + (lane >> 2);
        int k = ks * 16 + ((rr >> 1) << 3) + ((lane & 3) << 1);
        unsigned lo = __bfloat16_as_ushort(__float2bfloat16(w[((m * CIN + k    ) * 3 + kh) * 3 + kw]));
        unsigned hi = __bfloat16_as_ushort(__float2bfloat16(w[((m * CIN + k + 1) * 3 + kh) * 3 + kw]));
        r[rr] = lo | (hi << 16);
    }
    g_wa[i] = make_uint4(r[0], r[1], r[2], r[3]);
}

// ---------------------------------------------------------------------------
__device__ __forceinline__ void mma_bf16(float* c, const unsigned* a,
                                         unsigned b0, unsigned b1) {
    asm volatile(
        "mma.sync.aligned.m16n8k16.row.col.f32.bf16.bf16.f32 "
        "{%0,%1,%2,%3}, {%4,%5,%6,%7}, {%8,%9}, {%0,%1,%2,%3};\n"
        : "+f"(c[0]), "+f"(c[1]), "+f"(c[2]), "+f"(c[3])
        : "r"(a[0]), "r"(a[1]), "r"(a[2]), "r"(a[3]), "r"(b0), "r"(b1));
}

__device__ __forceinline__ void ldsm_x4(unsigned& r0, unsigned& r1,
                                        unsigned& r2, unsigned& r3, unsigned addr) {
    asm volatile("ldmatrix.sync.aligned.m8n8.x4.shared.b16 {%0,%1,%2,%3}, [%4];\n"
                 : "=r"(r0), "=r"(r1), "=r"(r2), "=r"(r3) : "r"(addr));
}

// ---------------------------------------------------------------------------
// Fused conv + bias + relu + spatial partial-sum.
// Grid (16 row-tiles, 512 imgs), 256 threads (8 warps).
// Block tile: 4 rows x 64 cols x 64 oc. Warp: 32 oc x 64 sp (one row).
// Smem: 6 rows x 66 cols (circular halo) x ic, ic padded to ICP=40
// (80B spatial stride -> conflict-free ldmatrix row fetches).
// ---------------------------------------------------------------------------
#define ICP 40

__global__ __launch_bounds__(256, 2)
void conv_pool_kernel(const float* __restrict__ x, const float* __restrict__ conv_b) {
    __shared__ alignas(16) __nv_bfloat16 tile[6 * 66 * ICP];   // 31680 B

    const int n   = blockIdx.y;
    const int rt  = blockIdx.x;
    const int h0  = rt * 4;
    const int tid = threadIdx.x;
    const float* xb = x + ((long)n << 17);

    // interior columns
    for (int idx = tid; idx < 6 * CIN * WW; idx += 256) {
        int w    = idx & 63;
        int rest = idx >> 6;
        int ic   = rest & 31;
        int rr   = rest >> 5;
        int gh   = (h0 + rr + 63) & 63;
        tile[(rr * 66 + w + 1) * ICP + ic] =
            __float2bfloat16(xb[(ic << 12) + (gh << 6) + w]);
    }
    // circular halo columns
    for (int idx = tid; idx < 6 * CIN * 2; idx += 256) {
        int side = idx & 1;
        int rest = idx >> 1;
        int ic   = rest & 31;
        int rr   = rest >> 5;
        int gh   = (h0 + rr + 63) & 63;
        int gw   = side ? 0 : 63;
        int c    = side ? 65 : 0;
        tile[(rr * 66 + c) * ICP + ic] =
            __float2bfloat16(xb[(ic << 12) + (gh << 6) + gw]);
    }
    __syncthreads();

    const int lane   = tid & 31;
    const int warp   = tid >> 5;
    const int warpOc = warp & 1;     // 2 oc groups of 32
    const int warpSp = warp >> 1;    // 4 sp groups = block-tile rows

    // ldmatrix lane address: col = nt*8 + (lane&7), ic = (lane>>3)*8
    unsigned sbase = (unsigned)__cvta_generic_to_shared(tile) +
                     (((warpSp * 66 + (lane & 7)) * ICP + ((lane >> 3) << 3)) << 1);

    float acc[8][2][4];
#pragma unroll
    for (int nt = 0; nt < 8; nt++)
#pragma unroll
        for (int mt = 0; mt < 2; mt++)
#pragma unroll
            for (int c = 0; c < 4; c++) acc[nt][mt][c] = 0.f;

    for (int kh = 0; kh < 3; kh++) {
        for (int kw = 0; kw < 3; kw++) {
            const int tap = kh * 3 + kw;
            // A fragments: [tap][ks][mtGlobal][lane]
            uint4 a00 = g_wa[((tap * 2 + 0) * 4 + warpOc * 2 + 0) * 32 + lane]; // ks0 mt0
            uint4 a01 = g_wa[((tap * 2 + 0) * 4 + warpOc * 2 + 1) * 32 + lane]; // ks0 mt1
            uint4 a10 = g_wa[((tap * 2 + 1) * 4 + warpOc * 2 + 0) * 32 + lane]; // ks1 mt0
            uint4 a11 = g_wa[((tap * 2 + 1) * 4 + warpOc * 2 + 1) * 32 + lane]; // ks1 mt1
            unsigned tapaddr = sbase + (unsigned)(((kh * 66 + kw) * ICP) << 1);
#pragma unroll
            for (int nt = 0; nt < 8; nt++) {
                unsigned b0, b1, b2, b3;
                ldsm_x4(b0, b1, b2, b3, tapaddr + nt * (8 * ICP * 2));
                mma_bf16(acc[nt][0], (const unsigned*)&a00, b0, b1);
                mma_bf16(acc[nt][1], (const unsigned*)&a01, b0, b1);
                mma_bf16(acc[nt][0], (const unsigned*)&a10, b2, b3);
                mma_bf16(acc[nt][1], (const unsigned*)&a11, b2, b3);
            }
        }
    }

    // epilogue: bias + relu + sum over spatial, reduce over (lane&3)
    const int rowa = lane >> 2;
#pragma unroll
    for (int mt = 0; mt < 2; mt++) {
        int oc = warpOc * 32 + mt * 16 + rowa;
        float bs0 = conv_b[oc];
        float bs1 = conv_b[oc + 8];
        float s0 = 0.f, s1 = 0.f;
#pragma unroll
        for (int nt = 0; nt < 8; nt++) {
            s0 += fmaxf(acc[nt][mt][0] + bs0, 0.f) + fmaxf(acc[nt][mt][1] + bs0, 0.f);
            s1 += fmaxf(acc[nt][mt][2] + bs1, 0.f) + fmaxf(acc[nt][mt][3] + bs1, 0.f);
        }
        s0 += __shfl_xor_sync(0xffffffffu, s0, 1);
        s0 += __shfl_xor_sync(0xffffffffu, s0, 2);
        s1 += __shfl_xor_sync(0xffffffffu, s1, 1);
        s1 += __shfl_xor_sync(0xffffffffu, s1, 2);
        if ((lane & 3) == 0) {
            int slot = rt * 4 + warpSp;
            g_partial[slot * (NIMG * COUT) + (n << 6) + oc]     = s0;
            g_partial[slot * (NIMG * COUT) + (n << 6) + oc + 8] = s1;
        }
    }
}

// ---------------------------------------------------------------------------
__global__ void reduce_nodes_kernel() {
    int i = blockIdx.x * blockDim.x + threadIdx.x;   // 32768
    float s = 0.f;
#pragma unroll
    for (int k = 0; k < NSLOT; k++) s += g_partial[k * (NIMG * COUT) + i];
    g_nodes[i] = s * (1.f / 4096.f);
}

// ---------------------------------------------------------------------------
// Graph MLP: one block per batch b; weights staged in smem; decomposition
// e1(i,j) = relu(a_i + c_j) with a = n@W_top + b1, c = n@W_bot.
// 256 threads = 4 node-groups g x 64 hid h.
// dyn smem float layout:
//   W1 0 (8192), W2 8192 (4096), OW1 12288 (4096), OW2 16384 (64),
//   B1 16448, B2 16512, OB1 16576, ob2 16640, sN 16704, sA 16960,
//   sC 17216, sE 17472 (1024), sM 18496, red 18752 -> total 18760 floats
// ---------------------------------------------------------------------------
#define MLP_DYN (18760 * 4)

__global__ __launch_bounds__(256)
void mlp_kernel(const float* __restrict__ e_w1, const float* __restrict__ e_b1,
                const float* __restrict__ e_w2, const float* __restrict__ e_b2,
                const float* __restrict__ o_w1, const float* __restrict__ o_b1,
                const float* __restrict__ o_w2, const float* __restrict__ o_b2,
                float* __restrict__ out) {
    extern __shared__ float ws[];
    float* W1  = ws;
    float* W2  = ws + 8192;
    float* OW1 = ws + 12288;
    float* OW2 = ws + 16384;
    float* B1  = ws + 16448;
    float* B2  = ws + 16512;
    float* OB1 = ws + 16576;
    float* sN  = ws + 16704;
    float* sA  = ws + 16960;
    float* sC  = ws + 17216;
    float* sE  = ws + 17472;   // [i][j][h] = [(i*4+j)*64+h]
    float* sM  = ws + 18496;
    float* red = ws + 18752;

    const int b   = blockIdx.x;
    const int tid = threadIdx.x;
    const int g   = tid >> 6;
    const int h   = tid & 63;

    for (int i = tid; i < 8192; i += 256) W1[i]  = e_w1[i];
    for (int i = tid; i < 4096; i += 256) W2[i]  = e_w2[i];
    for (int i = tid; i < 4096; i += 256) OW1[i] = o_w1[i];
    if (tid < 64) {
        OW2[tid] = o_w2[tid];
        B1[tid]  = e_b1[tid];
        B2[tid]  = e_b2[tid];
        OB1[tid] = o_b1[tid];
    }
    if (tid == 0) ws[16640] = o_b2[0];
    sN[g * 64 + h] = g_nodes[(g * 128 + b) * HID + h];
    __syncthreads();

    // a_g = n_g @ W_top + b1 ; c_g = n_g @ W_bot
    {
        float a0 = B1[h], a1 = 0.f, c0 = 0.f, c1 = 0.f;
#pragma unroll 8
        for (int k = 0; k < 64; k += 2) {
            float n0 = sN[g * 64 + k], n1 = sN[g * 64 + k + 1];
            a0 = fmaf(n0, W1[k * 64 + h], a0);
            a1 = fmaf(n1, W1[(k + 1) * 64 + h], a1);
            c0 = fmaf(n0, W1[(64 + k) * 64 + h], c0);
            c1 = fmaf(n1, W1[(64 + k + 1) * 64 + h], c1);
        }
        sA[g * 64 + h] = a0 + a1;
        sC[g * 64 + h] = c0 + c1;
    }
    __syncthreads();
    // e1[i=g][j][h] = relu(a_i + c_j)
    {
        float a = sA[g * 64 + h];
#pragma unroll
        for (int j = 0; j < 4; j++)
            sE[(g * 4 + j) * 64 + h] = fmaxf(a + sC[j * 64 + h], 0.f);
    }
    __syncthreads();
    // msg[j=g][h] = mean_i relu(e1[i][g] @ W2 + b2)
    {
        float m = 0.f;
        for (int i = 0; i < 4; i++) {
            float q0 = B2[h], q1 = 0.f;
            const float* e = sE + (i * 4 + g) * 64;
#pragma unroll 8
            for (int k = 0; k < 64; k += 2) {
                q0 = fmaf(e[k],     W2[k * 64 + h],       q0);
                q1 = fmaf(e[k + 1], W2[(k + 1) * 64 + h], q1);
            }
            m += fmaxf(q0 + q1, 0.f);
        }
        sM[g * 64 + h] = m * 0.25f;
    }
    __syncthreads();
    // o1 + final dot with o_w2
    {
        float q0 = OB1[h], q1 = 0.f;
#pragma unroll 8
        for (int k = 0; k < 64; k += 2) {
            q0 = fmaf(sM[g * 64 + k],     OW1[k * 64 + h],       q0);
            q1 = fmaf(sM[g * 64 + k + 1], OW1[(k + 1) * 64 + h], q1);
        }
        float v = fmaxf(q0 + q1, 0.f) * OW2[h];
#pragma unroll
        for (int m = 16; m >= 1; m >>= 1) v += __shfl_xor_sync(0xffffffffu, v, m);
        if ((tid & 31) == 0) red[tid >> 5] = v;
    }
    __syncthreads();
    if (tid < 4) out[b * 4 + tid] = red[2 * tid] + red[2 * tid + 1] + ws[16640];
}

// ---------------------------------------------------------------------------
extern "C" void kernel_launch(void* const* d_in, const int* in_sizes, int n_in,
                              void* d_out, int out_size) {
    const float* x      = (const float*)d_in[0];
    const float* conv_w = (const float*)d_in[1];
    const float* conv_b = (const float*)d_in[2];
    const float* e_w1   = (const float*)d_in[3];
    const float* e_b1   = (const float*)d_in[4];
    const float* e_w2   = (const float*)d_in[5];
    const float* e_b2   = (const float*)d_in[6];
    const float* o_w1   = (const float*)d_in[7];
    const float* o_b1   = (const float*)d_in[8];
    const float* o_w2   = (const float*)d_in[9];
    const float* o_b2   = (const float*)d_in[10];
    float* out = (float*)d_out;

    // idempotent, called every launch (no static guards per harness rules)
    cudaFuncSetAttribute(mlp_kernel,
                         cudaFuncAttributeMaxDynamicSharedMemorySize, MLP_DYN);

    prep_kernel<<<9, 256>>>(conv_w);

    dim3 grid(16, NIMG);
    conv_pool_kernel<<<grid, 256>>>(x, conv_b);

    reduce_nodes_kernel<<<(NIMG * COUT) / 256, 256>>>();

    mlp_kernel<<<128, 256, MLP_DYN>>>(e_w1, e_b1, e_w2, e_b2,
                                      o_w1, o_b1, o_w2, o_b2, out);
}